// round 1
// baseline (speedup 1.0000x reference)
#include <cuda_runtime.h>
#include <math.h>

// Problem constants
#define Bdim 16
#define Ndim 2048
#define Ddim 1024
#define Pdim 2048

// Scratch: Z holds logits+gumbel, then (in-place) unnormalized exp values.
// 16*2048*2048 floats = 268 MB. Static __device__ array (allocation-free rule).
__device__ float g_Z[(size_t)Bdim * Pdim * Ndim];
// Per-(b,n) 1/sum_exp, folded into K3 epilogue.
__device__ float g_inv[(size_t)Bdim * Ndim];

// ---------------------------------------------------------------------------
// K1: Z[b,p,n] = sum_d proto[p,d]*x[b,n,d]  - log(-log(u[b,p,n]))
// Register-blocked SGEMM: 128x128 tile, K-tile 16, 256 threads, 8x8 micro.
// grid = (N/128, P/128, B)
// ---------------------------------------------------------------------------
__global__ __launch_bounds__(256) void k1_logits(
    const float* __restrict__ x, const float* __restrict__ u,
    const float* __restrict__ proto)
{
    __shared__ __align__(16) float As[16][128];  // As[k][p]
    __shared__ __align__(16) float Bs[16][128];  // Bs[k][n]

    const int tid = threadIdx.x;
    const int bn = blockIdx.x, bp = blockIdx.y, b = blockIdx.z;
    const int tx = tid & 15;   // n direction (8 outputs)
    const int ty = tid >> 4;   // p direction (8 outputs)

    const float* Aptr = proto + (size_t)(bp * 128) * Ddim;
    const float* Bptr = x + ((size_t)b * Ndim + (size_t)bn * 128) * Ddim;

    float acc[8][8];
#pragma unroll
    for (int i = 0; i < 8; i++)
#pragma unroll
        for (int j = 0; j < 8; j++) acc[i][j] = 0.f;

    const int lr = tid >> 2;         // 0..63 (row)
    const int lk = (tid & 3) << 2;   // 0,4,8,12 (k offset)

    for (int k0 = 0; k0 < Ddim; k0 += 16) {
        float4 a0 = *(const float4*)(Aptr + (size_t)lr * Ddim + k0 + lk);
        float4 a1 = *(const float4*)(Aptr + (size_t)(lr + 64) * Ddim + k0 + lk);
        float4 b0 = *(const float4*)(Bptr + (size_t)lr * Ddim + k0 + lk);
        float4 b1 = *(const float4*)(Bptr + (size_t)(lr + 64) * Ddim + k0 + lk);
        __syncthreads();  // previous tile's compute done before overwrite
        As[lk + 0][lr] = a0.x; As[lk + 1][lr] = a0.y; As[lk + 2][lr] = a0.z; As[lk + 3][lr] = a0.w;
        As[lk + 0][lr + 64] = a1.x; As[lk + 1][lr + 64] = a1.y; As[lk + 2][lr + 64] = a1.z; As[lk + 3][lr + 64] = a1.w;
        Bs[lk + 0][lr] = b0.x; Bs[lk + 1][lr] = b0.y; Bs[lk + 2][lr] = b0.z; Bs[lk + 3][lr] = b0.w;
        Bs[lk + 0][lr + 64] = b1.x; Bs[lk + 1][lr + 64] = b1.y; Bs[lk + 2][lr + 64] = b1.z; Bs[lk + 3][lr + 64] = b1.w;
        __syncthreads();
#pragma unroll
        for (int kk = 0; kk < 16; kk++) {
            float4 ar0 = *(const float4*)&As[kk][ty * 8];
            float4 ar1 = *(const float4*)&As[kk][ty * 8 + 4];
            float4 br0 = *(const float4*)&Bs[kk][tx * 8];
            float4 br1 = *(const float4*)&Bs[kk][tx * 8 + 4];
            float ar[8] = {ar0.x, ar0.y, ar0.z, ar0.w, ar1.x, ar1.y, ar1.z, ar1.w};
            float br[8] = {br0.x, br0.y, br0.z, br0.w, br1.x, br1.y, br1.z, br1.w};
#pragma unroll
            for (int i = 0; i < 8; i++)
#pragma unroll
                for (int j = 0; j < 8; j++)
                    acc[i][j] = fmaf(ar[i], br[j], acc[i][j]);
        }
    }

    // Epilogue: add Gumbel noise g = -log(-log(u)) and store Z.
    const int prow = bp * 128 + ty * 8;
    const int ncol = bn * 128 + tx * 8;
#pragma unroll
    for (int i = 0; i < 8; i++) {
        size_t base = ((size_t)b * Pdim + prow + i) * (size_t)Ndim + ncol;
#pragma unroll
        for (int jj = 0; jj < 8; jj += 4) {
            float4 uu = *(const float4*)(u + base + jj);
            float4 o;
            o.x = acc[i][jj + 0] - __logf(-__logf(uu.x));
            o.y = acc[i][jj + 1] - __logf(-__logf(uu.y));
            o.z = acc[i][jj + 2] - __logf(-__logf(uu.z));
            o.w = acc[i][jj + 3] - __logf(-__logf(uu.w));
            *(float4*)(g_Z + base + jj) = o;
        }
    }
}

// ---------------------------------------------------------------------------
// K2: per-(b,n) softmax over p axis, in place. Stores UNNORMALIZED exp(v-m)
// and 1/sum in g_inv (normalization folded into K3 epilogue).
// grid = (N/256, B), 256 threads; thread owns one n column (coalesced over n).
// ---------------------------------------------------------------------------
__global__ __launch_bounds__(256) void k2_softmax()
{
    const int n = blockIdx.x * 256 + threadIdx.x;
    const int b = blockIdx.y;
    float* col = g_Z + (size_t)b * Pdim * Ndim + n;

    // pass 1: max
    float m = -3.4e38f;
#pragma unroll 8
    for (int p = 0; p < Pdim; p++) {
        float v = col[(size_t)p * Ndim];
        m = fmaxf(m, v);
    }
    // pass 2: exp + sum + store (single exp per element)
    float l = 0.f;
#pragma unroll 4
    for (int p = 0; p < Pdim; p++) {
        float v = col[(size_t)p * Ndim];
        float e = __expf(v - m);
        l += e;
        col[(size_t)p * Ndim] = e;
    }
    g_inv[(size_t)b * Ndim + n] = __frcp_rn(l);
}

// ---------------------------------------------------------------------------
// K3: out[b,n,d] = inv[b,n] * sum_p Z[b,p,n] * proto[p,d]
// A operand Z is [p][n] (already K-major for M=n), B operand proto [p][d].
// 128x128 tile, K-tile 16, 256 threads, 8x8 micro. grid = (D/128, N/128, B)
// ---------------------------------------------------------------------------
__global__ __launch_bounds__(256) void k3_combine(
    const float* __restrict__ proto, float* __restrict__ out)
{
    __shared__ __align__(16) float As[16][128];  // As[k][n]
    __shared__ __align__(16) float Bs[16][128];  // Bs[k][d]

    const int tid = threadIdx.x;
    const int bd = blockIdx.x, bn = blockIdx.y, b = blockIdx.z;
    const int tx = tid & 15;   // d direction
    const int ty = tid >> 4;   // n direction

    const int n0 = bn * 128;
    const int d0 = bd * 128;

    float acc[8][8];
#pragma unroll
    for (int i = 0; i < 8; i++)
#pragma unroll
        for (int j = 0; j < 8; j++) acc[i][j] = 0.f;

    const int lrow = tid >> 4;        // 0..15 (k row within tile)
    const int lc = (tid & 15) << 2;   // 0..60 step 4 (col offset)

    for (int p0 = 0; p0 < Pdim; p0 += 16) {
        const float* Zrow = g_Z + ((size_t)b * Pdim + p0 + lrow) * (size_t)Ndim + n0;
        const float* Prow = proto + (size_t)(p0 + lrow) * Ddim + d0;
        float4 a0 = *(const float4*)(Zrow + lc);
        float4 a1 = *(const float4*)(Zrow + lc + 64);
        float4 b0 = *(const float4*)(Prow + lc);
        float4 b1 = *(const float4*)(Prow + lc + 64);
        __syncthreads();
        *(float4*)&As[lrow][lc] = a0;
        *(float4*)&As[lrow][lc + 64] = a1;
        *(float4*)&Bs[lrow][lc] = b0;
        *(float4*)&Bs[lrow][lc + 64] = b1;
        __syncthreads();
#pragma unroll
        for (int kk = 0; kk < 16; kk++) {
            float4 ar0 = *(const float4*)&As[kk][ty * 8];
            float4 ar1 = *(const float4*)&As[kk][ty * 8 + 4];
            float4 br0 = *(const float4*)&Bs[kk][tx * 8];
            float4 br1 = *(const float4*)&Bs[kk][tx * 8 + 4];
            float ar[8] = {ar0.x, ar0.y, ar0.z, ar0.w, ar1.x, ar1.y, ar1.z, ar1.w};
            float br[8] = {br0.x, br0.y, br0.z, br0.w, br1.x, br1.y, br1.z, br1.w};
#pragma unroll
            for (int i = 0; i < 8; i++)
#pragma unroll
                for (int j = 0; j < 8; j++)
                    acc[i][j] = fmaf(ar[i], br[j], acc[i][j]);
        }
    }

    // Epilogue: scale each n-row by its 1/sum and store.
    const int nrow = n0 + ty * 8;
    const int dcol = d0 + tx * 8;
#pragma unroll
    for (int i = 0; i < 8; i++) {
        float s = g_inv[(size_t)b * Ndim + nrow + i];
        size_t base = ((size_t)b * Ndim + nrow + i) * (size_t)Ddim + dcol;
        float4 o0, o1;
        o0.x = acc[i][0] * s; o0.y = acc[i][1] * s; o0.z = acc[i][2] * s; o0.w = acc[i][3] * s;
        o1.x = acc[i][4] * s; o1.y = acc[i][5] * s; o1.z = acc[i][6] * s; o1.w = acc[i][7] * s;
        *(float4*)(out + base) = o0;
        *(float4*)(out + base + 4) = o1;
    }
}

extern "C" void kernel_launch(void* const* d_in, const int* in_sizes, int n_in,
                              void* d_out, int out_size)
{
    (void)in_sizes; (void)n_in; (void)out_size;
    const float* x     = (const float*)d_in[0];  // [B, N, D]
    const float* u     = (const float*)d_in[1];  // [B, P, N]
    const float* proto = (const float*)d_in[2];  // [P, D]
    float* out = (float*)d_out;                  // [B, N, D]

    dim3 g1(Ndim / 128, Pdim / 128, Bdim);
    k1_logits<<<g1, 256>>>(x, u, proto);

    dim3 g2(Ndim / 256, Bdim);
    k2_softmax<<<g2, 256>>>();

    dim3 g3(Ddim / 128, Ndim / 128, Bdim);
    k3_combine<<<g3, 256>>>(proto, out);
}

// round 3
// speedup vs baseline: 2.7880x; 2.7880x over previous
#include <cuda_runtime.h>
#include <cuda_bf16.h>
#include <cstdint>

#define Bdim 16
#define Ndim 2048
#define Ddim 1024
#define Pdim 2048

// ---------------- device scratch (static; allocation-free rule) ----------------
__device__ __align__(256) __nv_bfloat16 g_xh[(size_t)Bdim * Ndim * Ddim];   // x hi  [b][n][d]
__device__ __align__(256) __nv_bfloat16 g_xl[(size_t)Bdim * Ndim * Ddim];   // x lo
__device__ __align__(256) __nv_bfloat16 g_ph[(size_t)Pdim * Ddim];          // proto hi [p][d]
__device__ __align__(256) __nv_bfloat16 g_pl[(size_t)Pdim * Ddim];
__device__ __align__(256) __nv_bfloat16 g_pth[(size_t)Ddim * Pdim];         // protoT hi [d][p]
__device__ __align__(256) __nv_bfloat16 g_ptl[(size_t)Ddim * Pdim];
__device__ __align__(256) float         g_ZT[(size_t)Bdim * Ndim * Pdim];   // Z^T [b][n][p]
__device__ __align__(256) __nv_bfloat16 g_aTh[(size_t)Bdim * Ndim * Pdim];  // exp hi [b][n][p]
__device__ __align__(256) __nv_bfloat16 g_aTl[(size_t)Bdim * Ndim * Pdim];  // exp lo
__device__ __align__(256) float         g_inv[(size_t)Bdim * Ndim];

// ---------------- baseline-PTX helpers (sm_80-class only; no 'a' features) -----
__device__ __forceinline__ uint32_t smem_u32_of(const void* p) {
    uint32_t a;
    asm("{ .reg .u64 t; cvta.to.shared.u64 t, %1; cvt.u32.u64 %0, t; }" : "=r"(a) : "l"(p));
    return a;
}
__device__ __forceinline__ void cpasync16(uint32_t s, const void* g) {
    asm volatile("cp.async.cg.shared.global [%0], [%1], 16;" :: "r"(s), "l"(g));
}
#define CP_COMMIT() asm volatile("cp.async.commit_group;")
#define CP_WAIT(n)  asm volatile("cp.async.wait_group %0;" :: "n"(n))

__device__ __forceinline__ void ldsm4(uint32_t* r, uint32_t addr) {
    asm volatile("ldmatrix.sync.aligned.m8n8.x4.shared.b16 {%0,%1,%2,%3}, [%4];"
                 : "=r"(r[0]), "=r"(r[1]), "=r"(r[2]), "=r"(r[3]) : "r"(addr));
}
__device__ __forceinline__ void mma16816(float* c, const uint32_t* a, const uint32_t* b) {
    asm volatile("mma.sync.aligned.m16n8k16.row.col.f32.bf16.bf16.f32 "
                 "{%0,%1,%2,%3}, {%4,%5,%6,%7}, {%8,%9}, {%0,%1,%2,%3};"
                 : "+f"(c[0]), "+f"(c[1]), "+f"(c[2]), "+f"(c[3])
                 : "r"(a[0]), "r"(a[1]), "r"(a[2]), "r"(a[3]), "r"(b[0]), "r"(b[1]));
}

// ---------------- tiling constants ----------------
static constexpr int KT = 32;                 // bf16 k per stage
static constexpr int ROWB = 80;               // padded smem row bytes (64 data + 16 pad)
static constexpr int TILE_B = 128 * ROWB;     // 10240 per operand tile
static constexpr int STAGE_B = 4 * TILE_B;    // Ah Al Bh Bl = 40960
static constexpr int DYN_SMEM = 2 * STAGE_B;  // 81920 (u-tile 67584 overlaps)

// load one stage (4 tiles x 128 rows x 64B), 8 cp.async per thread
__device__ __forceinline__ void load_stage(
    const __nv_bfloat16* gAh, const __nv_bfloat16* gAl,
    const __nv_bfloat16* gBh, const __nv_bfloat16* gBl,
    size_t Ks, int k0, uint32_t sbase, int tid)
{
    const __nv_bfloat16* G[4] = {gAh, gAl, gBh, gBl};
    const int q = tid & 3;            // 16B chunk within 64B row
    const int r0 = tid >> 2;          // 0..63
#pragma unroll
    for (int i = 0; i < 8; i++) {
        const int tile = i >> 1;
        const int r = (i & 1) * 64 + r0;
        cpasync16(sbase + tile * TILE_B + r * ROWB + q * 16,
                  G[tile] + (size_t)r * Ks + k0 + q * 8);
    }
}

// compute one k32 stage: 2 k-steps x (4 m-frags x 4 n-frags x 3 split-MMAs)
__device__ __forceinline__ void compute_stage(
    uint32_t sbase, int wm, int wn, uint32_t aoff, uint32_t boff,
    float acc[4][4][4])
{
    const uint32_t sAh = sbase;
    const uint32_t sAl = sbase + TILE_B;
    const uint32_t sBh = sbase + 2 * TILE_B;
    const uint32_t sBl = sbase + 3 * TILE_B;
#pragma unroll
    for (int ks = 0; ks < 2; ks++) {
        const uint32_t kb = ks * 32;   // 16 bf16 = 32 bytes
        uint32_t bh[8], bl[8];
#pragma unroll
        for (int f = 0; f < 2; f++) {
            uint32_t off = (wn * 32 + f * 16) * ROWB + kb + boff;
            ldsm4(bh + f * 4, sBh + off);
            ldsm4(bl + f * 4, sBl + off);
        }
#pragma unroll
        for (int mf = 0; mf < 4; mf++) {
            uint32_t off = (wm * 64 + mf * 16) * ROWB + kb + aoff;
            uint32_t ah[4], al[4];
            ldsm4(ah, sAh + off);
            ldsm4(al, sAl + off);
#pragma unroll
            for (int nf = 0; nf < 4; nf++) {
                mma16816(acc[mf][nf], ah, bh + nf * 2);
                mma16816(acc[mf][nf], ah, bl + nf * 2);
                mma16816(acc[mf][nf], al, bh + nf * 2);
            }
        }
    }
}

__device__ __forceinline__ void gemm_mainloop(
    const __nv_bfloat16* gAh, const __nv_bfloat16* gAl,
    const __nv_bfloat16* gBh, const __nv_bfloat16* gBl,
    size_t Ks, int T, uint32_t smem_b, int tid, float acc[4][4][4])
{
    const int lane = tid & 31, wid = tid >> 5;
    const int wm = wid & 1, wn = wid >> 1;
    const uint32_t aoff = (uint32_t)((lane & 15) * ROWB + ((lane & 16) ? 16 : 0));
    const uint32_t boff = (uint32_t)(((lane & 7) + ((lane & 16) ? 8 : 0)) * ROWB
                                     + ((lane & 8) ? 16 : 0));
#pragma unroll
    for (int mf = 0; mf < 4; mf++)
#pragma unroll
        for (int nf = 0; nf < 4; nf++)
#pragma unroll
            for (int e = 0; e < 4; e++) acc[mf][nf][e] = 0.f;

    load_stage(gAh, gAl, gBh, gBl, Ks, 0, smem_b, tid);
    CP_COMMIT();
    load_stage(gAh, gAl, gBh, gBl, Ks, KT, smem_b + STAGE_B, tid);
    CP_COMMIT();

    for (int t = 0; t < T; t++) {
        if (t == T - 1) { CP_WAIT(0); } else { CP_WAIT(1); }
        __syncthreads();
        compute_stage(smem_b + (t & 1) * STAGE_B, wm, wn, aoff, boff, acc);
        __syncthreads();
        if (t + 2 < T) {
            load_stage(gAh, gAl, gBh, gBl, Ks, (t + 2) * KT, smem_b + (t & 1) * STAGE_B, tid);
            CP_COMMIT();
        }
    }
}

// ---------------------------------------------------------------------------
// conv kernels: fp32 -> bf16 hi/lo splits
// ---------------------------------------------------------------------------
__global__ __launch_bounds__(256) void conv_x(const float* __restrict__ x) {
    size_t i = ((size_t)blockIdx.x * 256 + threadIdx.x) * 4;
    float4 v = *(const float4*)(x + i);
    __nv_bfloat16 h0 = __float2bfloat16(v.x), h1 = __float2bfloat16(v.y);
    __nv_bfloat16 h2 = __float2bfloat16(v.z), h3 = __float2bfloat16(v.w);
    __nv_bfloat162* oh = (__nv_bfloat162*)(g_xh + i);
    __nv_bfloat162* ol = (__nv_bfloat162*)(g_xl + i);
    oh[0] = __nv_bfloat162{h0, h1}; oh[1] = __nv_bfloat162{h2, h3};
    ol[0] = __nv_bfloat162{__float2bfloat16(v.x - __bfloat162float(h0)),
                           __float2bfloat16(v.y - __bfloat162float(h1))};
    ol[1] = __nv_bfloat162{__float2bfloat16(v.z - __bfloat162float(h2)),
                           __float2bfloat16(v.w - __bfloat162float(h3))};
}
__global__ __launch_bounds__(256) void conv_p(const float* __restrict__ proto) {
    int idx = blockIdx.x * 256 + threadIdx.x;
    int p = idx / Ddim, d = idx % Ddim;
    float v = proto[idx];
    __nv_bfloat16 h = __float2bfloat16(v);
    __nv_bfloat16 l = __float2bfloat16(v - __bfloat162float(h));
    g_ph[idx] = h; g_pl[idx] = l;
    g_pth[(size_t)d * Pdim + p] = h; g_ptl[(size_t)d * Pdim + p] = l;
}

// ---------------------------------------------------------------------------
// K1: Z^T[b][n][p] = x.proto^T + gumbel.  M=n(128), N=p(128), K=d.
// ---------------------------------------------------------------------------
__global__ __launch_bounds__(256) void k1_logits(const float* __restrict__ u) {
    extern __shared__ char smem[];
    const uint32_t smem_b = smem_u32_of(smem);
    const int tid = threadIdx.x, lane = tid & 31, wid = tid >> 5;
    const int wm = wid & 1, wn = wid >> 1;
    const int bn = blockIdx.x, bp = blockIdx.y, b = blockIdx.z;

    float acc[4][4][4];
    gemm_mainloop(g_xh + ((size_t)b * Ndim + bn * 128) * Ddim,
                  g_xl + ((size_t)b * Ndim + bn * 128) * Ddim,
                  g_ph + (size_t)(bp * 128) * Ddim,
                  g_pl + (size_t)(bp * 128) * Ddim,
                  (size_t)Ddim, Ddim / KT, smem_b, tid, acc);

    // stage u tile [p0..p0+127][n0..n0+127] into smem (stride 132 floats)
    __syncthreads();
    float* u_s = (float*)smem;
    const float* ug = u + ((size_t)b * Pdim + (size_t)bp * 128) * Ndim + bn * 128;
#pragma unroll
    for (int j = 0; j < 16; j++) {
        int idx = tid + j * 256;        // 0..4095 float4s
        int row = idx >> 5, c4 = idx & 31;
        float4 v = *(const float4*)(ug + (size_t)row * Ndim + c4 * 4);
        *(float4*)(u_s + row * 132 + c4 * 4) = v;
    }
    __syncthreads();

    const int gID = lane >> 2, tg = lane & 3;
#pragma unroll
    for (int mf = 0; mf < 4; mf++) {
#pragma unroll
        for (int r2 = 0; r2 < 2; r2++) {
            const int nl = wm * 64 + mf * 16 + gID + r2 * 8;
            const size_t rowbase = ((size_t)b * Ndim + bn * 128 + nl) * Pdim + bp * 128;
#pragma unroll
            for (int nf = 0; nf < 4; nf++) {
                const int pl = wn * 32 + nf * 8 + tg * 2;
                float u0 = u_s[pl * 132 + nl];
                float u1 = u_s[(pl + 1) * 132 + nl];
                float2 z;
                z.x = acc[mf][nf][r2 * 2 + 0] - __logf(-__logf(u0));
                z.y = acc[mf][nf][r2 * 2 + 1] - __logf(-__logf(u1));
                *(float2*)&g_ZT[rowbase + pl] = z;
            }
        }
    }
}

// ---------------------------------------------------------------------------
// K2: warp-per-(b,n) softmax over p; emit bf16 hi/lo of exp + 1/sum
// ---------------------------------------------------------------------------
__global__ __launch_bounds__(256) void k2_softmax() {
    int wid = threadIdx.x >> 5, lane = threadIdx.x & 31;
    int n = blockIdx.x * 8 + wid, b = blockIdx.y;
    size_t rb = ((size_t)b * Ndim + n) * Pdim;
    const float4* row = (const float4*)(g_ZT + rb);
    float m = -3.4e38f;
#pragma unroll
    for (int i = 0; i < 16; i++) {
        float4 v = row[lane + 32 * i];
        m = fmaxf(m, fmaxf(fmaxf(v.x, v.y), fmaxf(v.z, v.w)));
    }
#pragma unroll
    for (int o = 16; o > 0; o >>= 1) m = fmaxf(m, __shfl_xor_sync(0xFFFFFFFFu, m, o));
    float s = 0.f;
    __nv_bfloat162* oh = (__nv_bfloat162*)(g_aTh + rb);
    __nv_bfloat162* ol = (__nv_bfloat162*)(g_aTl + rb);
#pragma unroll 4
    for (int i = 0; i < 16; i++) {
        int i4 = lane + 32 * i;
        float4 v = row[i4];
        float e0 = __expf(v.x - m), e1 = __expf(v.y - m);
        float e2 = __expf(v.z - m), e3 = __expf(v.w - m);
        s += (e0 + e1) + (e2 + e3);
        __nv_bfloat16 h0 = __float2bfloat16(e0), h1 = __float2bfloat16(e1);
        __nv_bfloat16 h2 = __float2bfloat16(e2), h3 = __float2bfloat16(e3);
        oh[i4 * 2 + 0] = __nv_bfloat162{h0, h1};
        oh[i4 * 2 + 1] = __nv_bfloat162{h2, h3};
        ol[i4 * 2 + 0] = __nv_bfloat162{__float2bfloat16(e0 - __bfloat162float(h0)),
                                        __float2bfloat16(e1 - __bfloat162float(h1))};
        ol[i4 * 2 + 1] = __nv_bfloat162{__float2bfloat16(e2 - __bfloat162float(h2)),
                                        __float2bfloat16(e3 - __bfloat162float(h3))};
    }
#pragma unroll
    for (int o = 16; o > 0; o >>= 1) s += __shfl_xor_sync(0xFFFFFFFFu, s, o);
    if (lane == 0) g_inv[(size_t)b * Ndim + n] = 1.0f / s;
}

// ---------------------------------------------------------------------------
// K3: out[b][n][d] = inv[b][n] * sum_p a^T[n][p] protoT[d][p].  M=n, N=d, K=p.
// ---------------------------------------------------------------------------
__global__ __launch_bounds__(256) void k3_combine(float* __restrict__ out) {
    extern __shared__ char smem[];
    const uint32_t smem_b = smem_u32_of(smem);
    const int tid = threadIdx.x, lane = tid & 31, wid = tid >> 5;
    const int wm = wid & 1, wn = wid >> 1;
    const int dt = blockIdx.x, nt = blockIdx.y, b = blockIdx.z;

    float acc[4][4][4];
    gemm_mainloop(g_aTh + ((size_t)b * Ndim + nt * 128) * Pdim,
                  g_aTl + ((size_t)b * Ndim + nt * 128) * Pdim,
                  g_pth + (size_t)(dt * 128) * Pdim,
                  g_ptl + (size_t)(dt * 128) * Pdim,
                  (size_t)Pdim, Pdim / KT, smem_b, tid, acc);

    const int gID = lane >> 2, tg = lane & 3;
#pragma unroll
    for (int mf = 0; mf < 4; mf++) {
#pragma unroll
        for (int r2 = 0; r2 < 2; r2++) {
            const int nl = wm * 64 + mf * 16 + gID + r2 * 8;
            const int n_g = nt * 128 + nl;
            const float sc = g_inv[(size_t)b * Ndim + n_g];
            const size_t rowbase = ((size_t)b * Ndim + n_g) * Ddim + dt * 128;
#pragma unroll
            for (int nf = 0; nf < 4; nf++) {
                const int dl = wn * 32 + nf * 8 + tg * 2;
                float2 o;
                o.x = acc[mf][nf][r2 * 2 + 0] * sc;
                o.y = acc[mf][nf][r2 * 2 + 1] * sc;
                *(float2*)&out[rowbase + dl] = o;
            }
        }
    }
}

// ---------------------------------------------------------------------------
extern "C" void kernel_launch(void* const* d_in, const int* in_sizes, int n_in,
                              void* d_out, int out_size)
{
    (void)in_sizes; (void)n_in; (void)out_size;
    const float* x     = (const float*)d_in[0];  // [B, N, D]
    const float* u     = (const float*)d_in[1];  // [B, P, N]
    const float* proto = (const float*)d_in[2];  // [P, D]
    float* out = (float*)d_out;                  // [B, N, D]

    cudaFuncSetAttribute(k1_logits, cudaFuncAttributeMaxDynamicSharedMemorySize, DYN_SMEM);
    cudaFuncSetAttribute(k3_combine, cudaFuncAttributeMaxDynamicSharedMemorySize, DYN_SMEM);

    conv_x<<<(int)(((size_t)Bdim * Ndim * Ddim) / 4 / 256), 256>>>(x);
    conv_p<<<(Pdim * Ddim) / 256, 256>>>(proto);

    dim3 g1(Ndim / 128, Pdim / 128, Bdim);
    k1_logits<<<g1, 256, DYN_SMEM>>>(u);

    dim3 g2(Ndim / 8, Bdim);
    k2_softmax<<<g2, 256>>>();

    dim3 g3(Ddim / 128, Ndim / 128, Bdim);
    k3_combine<<<g3, 256, DYN_SMEM>>>(out);
}